// round 1
// baseline (speedup 1.0000x reference)
#include <cuda_runtime.h>

#define NT 512
#define NB 128

// Shared memory layout (floats):
//  W2s  [0      .. 4096)   64x64
//  Pa   [4096   .. 8192)   power ping
//  Pb   [8192   .. 12288)  power pong
//  W1s  [12288  .. 23040)  64x168 padded W1 (147 -> 168 = 3*56, kx padded 7->8)
//  W1f  [23040  .. 33792)  64x168 folded A*W1
//  xs   [33792  .. 36816)  2 rows x 3 x 7 x 72 input tiles
//  sa   [36816  .. 36880)
//  sb   [36880  .. 36944)
//  b1s  [36944  .. 37008)
//  b2s  [37008  .. 37072)
//  beff [37072  .. 37136)
#define SM_FLOATS 37136

extern __shared__ float sm[];

#define FMA4(acc, s, bv)                    \
    acc[0] = fmaf((s), (bv).x, acc[0]);     \
    acc[1] = fmaf((s), (bv).y, acc[1]);     \
    acc[2] = fmaf((s), (bv).z, acc[2]);     \
    acc[3] = fmaf((s), (bv).w, acc[3]);

// C = A * B, 64x64x64, all row-major in shared. 512 threads, 2x4 tiles.
__device__ __forceinline__ void gemm64(const float* __restrict__ A,
                                       const float* __restrict__ B,
                                       float* __restrict__ C, int t)
{
    const int cq = t & 15;      // column quad
    const int op = t >> 4;      // row pair
    const int c0 = cq * 4;
    const int o0 = op * 2;
    float acc0[4] = {0.f, 0.f, 0.f, 0.f};
    float acc1[4] = {0.f, 0.f, 0.f, 0.f};
#pragma unroll
    for (int k = 0; k < 64; k += 4) {
        float4 a0 = *(const float4*)(A + o0 * 64 + k);
        float4 a1 = *(const float4*)(A + (o0 + 1) * 64 + k);
        float4 r0 = *(const float4*)(B + (k + 0) * 64 + c0);
        float4 r1 = *(const float4*)(B + (k + 1) * 64 + c0);
        float4 r2 = *(const float4*)(B + (k + 2) * 64 + c0);
        float4 r3 = *(const float4*)(B + (k + 3) * 64 + c0);
        FMA4(acc0, a0.x, r0); FMA4(acc0, a0.y, r1);
        FMA4(acc0, a0.z, r2); FMA4(acc0, a0.w, r3);
        FMA4(acc1, a1.x, r0); FMA4(acc1, a1.y, r1);
        FMA4(acc1, a1.z, r2); FMA4(acc1, a1.w, r3);
    }
    *(float4*)(C + o0 * 64 + c0)       = make_float4(acc0[0], acc0[1], acc0[2], acc0[3]);
    *(float4*)(C + (o0 + 1) * 64 + c0) = make_float4(acc1[0], acc1[1], acc1[2], acc1[3]);
}

// sout[o] = sum_k A[o][k]*vin[k] + addv[o]   (warp-per-4-rows, conflict-free)
__device__ __forceinline__ void affvec(const float* __restrict__ A,
                                       const float* __restrict__ vin,
                                       const float* __restrict__ addv,
                                       float* __restrict__ sout, int t)
{
    const int w = t >> 5, l = t & 31;
#pragma unroll
    for (int j = 0; j < 4; ++j) {
        const int o = w * 4 + j;
        float p = A[o * 64 + l] * vin[l] + A[o * 64 + 32 + l] * vin[32 + l];
#pragma unroll
        for (int off = 16; off; off >>= 1)
            p += __shfl_xor_sync(0xffffffffu, p, off);
        if (l == 0) sout[o] = p + addv[o];
    }
}

__global__ void __launch_bounds__(NT, 1)
fused_conv_power(const float* __restrict__ x,
                 const float* __restrict__ W1,
                 const float* __restrict__ b1,
                 const float* __restrict__ W2,
                 const float* __restrict__ b2,
                 float* __restrict__ out)
{
    float* W2s  = sm;
    float* Pa   = sm + 4096;
    float* Pb   = sm + 8192;
    float* W1s  = sm + 12288;
    float* W1f  = sm + 23040;
    float* xs   = sm + 33792;
    float* sa   = sm + 36816;
    float* sb   = sm + 36880;
    float* b1s  = sm + 36944;
    float* b2s  = sm + 37008;
    float* beff = sm + 37072;

    const int t   = threadIdx.x;
    const int bid = blockIdx.x;

    // rows (b, y) handled by this block
    const int r0  = bid * 2;
    const int bb0 = r0 >> 6, y0 = r0 & 63;
    const int bb1 = (r0 + 1) >> 6, y1 = (r0 + 1) & 63;

    // ---- stage inputs into shared ----
    for (int i = t; i < 4096; i += NT) { float v = W2[i]; W2s[i] = v; Pa[i] = v; }
    for (int i = t; i < 64; i += NT)   { b1s[i] = b1[i]; float v = b2[i]; b2s[i] = v; sa[i] = v; }
    for (int i = t; i < 64 * 168; i += NT) {
        int m = i / 168, jp = i % 168;
        int ii = jp / 56, r = jp % 56, ky = r / 8, kx = r % 8;
        W1s[i] = (kx < 7) ? W1[m * 147 + ii * 49 + ky * 7 + kx] : 0.0f;
    }
    // input tiles for this block's two output rows: [row][i][ky][72]
    for (int i = t; i < 3024; i += NT) {
        int row = i / 1512, rem = i % 1512;
        int ii = rem / 504, rem2 = rem % 504;
        int ky = rem2 / 72, xx = rem2 % 72;
        int bb = row ? bb1 : bb0;
        int yy = (row ? y1 : y0) + ky;
        xs[i] = (xx < 70) ? x[((bb * 3 + ii) * 70 + yy) * 70 + xx] : 0.0f;
    }
    __syncthreads();

    // ---- affine power chain: T = (P, s), T_200 via square & multiply ----
    // 200 = 0b11001000 -> ops: sq,mul,sq,sq,sq,mul,sq,sq,sq  (mul at steps 1 and 5)
    float* cur  = Pa; float* nxt  = Pb;
    float* scur = sa; float* snxt = sb;
#pragma unroll 1
    for (int st = 0; st < 9; ++st) {
        const bool ismul = ((0x22u >> st) & 1u) != 0u;
        const float* Am = ismul ? W2s : cur;
        gemm64(Am, cur, nxt, t);                                   // P' = Am * P
        affvec(Am, scur, ismul ? b2s : scur, snxt, t);             // s' = Am*s + (b2 | s)
        __syncthreads();
        float* tp = cur; cur = nxt; nxt = tp;
        tp = scur; scur = snxt; snxt = tp;
    }
    // cur = A = W2^200, scur = sA = sum_{k<200} W2^k b2

    // ---- fold: W1f = A * W1s  (64 x 168, K=64) ----
    for (int tile = t; tile < 32 * 42; tile += NT) {
        int op = tile / 42, jq = tile % 42;
        int o0 = op * 2, j0 = jq * 4;
        float acc0[4] = {0.f, 0.f, 0.f, 0.f};
        float acc1[4] = {0.f, 0.f, 0.f, 0.f};
#pragma unroll
        for (int k = 0; k < 64; k += 4) {
            float4 a0 = *(const float4*)(cur + o0 * 64 + k);
            float4 a1 = *(const float4*)(cur + (o0 + 1) * 64 + k);
            float4 v0 = *(const float4*)(W1s + (k + 0) * 168 + j0);
            float4 v1 = *(const float4*)(W1s + (k + 1) * 168 + j0);
            float4 v2 = *(const float4*)(W1s + (k + 2) * 168 + j0);
            float4 v3 = *(const float4*)(W1s + (k + 3) * 168 + j0);
            FMA4(acc0, a0.x, v0); FMA4(acc0, a0.y, v1);
            FMA4(acc0, a0.z, v2); FMA4(acc0, a0.w, v3);
            FMA4(acc1, a1.x, v0); FMA4(acc1, a1.y, v1);
            FMA4(acc1, a1.z, v2); FMA4(acc1, a1.w, v3);
        }
        *(float4*)(W1f + o0 * 168 + j0)       = make_float4(acc0[0], acc0[1], acc0[2], acc0[3]);
        *(float4*)(W1f + (o0 + 1) * 168 + j0) = make_float4(acc1[0], acc1[1], acc1[2], acc1[3]);
    }
    // beff = A*b1 + sA
    affvec(cur, b1s, scur, beff, t);
    __syncthreads();

    // ---- fused conv with folded weights: out = conv(x, W1f) + beff ----
    const int xq = t & 15, opr = t >> 4;
    const int x0 = xq * 4, o0 = opr * 2;

    float acc[2][2][4];
#pragma unroll
    for (int r = 0; r < 2; ++r)
#pragma unroll
        for (int oo = 0; oo < 2; ++oo) {
            float bv = beff[o0 + oo];
#pragma unroll
            for (int xi = 0; xi < 4; ++xi) acc[r][oo][xi] = bv;
        }

#pragma unroll 1
    for (int ii = 0; ii < 3; ++ii) {
#pragma unroll 1
        for (int ky = 0; ky < 7; ++ky) {
            float xw[2][12];
#pragma unroll
            for (int r = 0; r < 2; ++r) {
                const float* p = xs + (r * 21 + ii * 7 + ky) * 72 + x0;
                float4 u0 = *(const float4*)(p);
                float4 u1 = *(const float4*)(p + 4);
                float4 u2 = *(const float4*)(p + 8);
                xw[r][0] = u0.x; xw[r][1] = u0.y; xw[r][2]  = u0.z; xw[r][3]  = u0.w;
                xw[r][4] = u1.x; xw[r][5] = u1.y; xw[r][6]  = u1.z; xw[r][7]  = u1.w;
                xw[r][8] = u2.x; xw[r][9] = u2.y; xw[r][10] = u2.z; xw[r][11] = u2.w;
            }
            float wv[2][8];
#pragma unroll
            for (int oo = 0; oo < 2; ++oo) {
                const float* p = W1f + (o0 + oo) * 168 + ii * 56 + ky * 8;
                float4 w0 = *(const float4*)(p);
                float4 w1 = *(const float4*)(p + 4);
                wv[oo][0] = w0.x; wv[oo][1] = w0.y; wv[oo][2] = w0.z; wv[oo][3] = w0.w;
                wv[oo][4] = w1.x; wv[oo][5] = w1.y; wv[oo][6] = w1.z; wv[oo][7] = w1.w;
            }
#pragma unroll
            for (int kx = 0; kx < 7; ++kx)
#pragma unroll
                for (int r = 0; r < 2; ++r)
#pragma unroll
                    for (int oo = 0; oo < 2; ++oo)
#pragma unroll
                        for (int xi = 0; xi < 4; ++xi)
                            acc[r][oo][xi] = fmaf(wv[oo][kx], xw[r][kx + xi], acc[r][oo][xi]);
        }
    }

    // ---- store: out[b][o][y][x] ----
#pragma unroll
    for (int r = 0; r < 2; ++r) {
        const int bb = r ? bb1 : bb0;
        const int yy = r ? y1 : y0;
#pragma unroll
        for (int oo = 0; oo < 2; ++oo) {
            float4 v = make_float4(acc[r][oo][0], acc[r][oo][1], acc[r][oo][2], acc[r][oo][3]);
            *(float4*)(out + ((bb * 64 + (o0 + oo)) * 64 + yy) * 64 + x0) = v;
        }
    }
}

extern "C" void kernel_launch(void* const* d_in, const int* in_sizes, int n_in,
                              void* d_out, int out_size)
{
    (void)in_sizes; (void)n_in; (void)out_size;
    const float* x  = (const float*)d_in[0];
    const float* W1 = (const float*)d_in[1];
    const float* b1 = (const float*)d_in[2];
    const float* W2 = (const float*)d_in[3];
    const float* b2 = (const float*)d_in[4];
    float* out = (float*)d_out;

    const size_t smem = (size_t)SM_FLOATS * sizeof(float);
    cudaFuncSetAttribute(fused_conv_power,
                         cudaFuncAttributeMaxDynamicSharedMemorySize, (int)smem);
    fused_conv_power<<<NB, NT, smem>>>(x, W1, b1, W2, b2, out);
}